// round 9
// baseline (speedup 1.0000x reference)
#include <cuda_runtime.h>
#include <math.h>

#define NX 400
#define NY 400
#define NC (NX*NY)
#define STEPS 300
#define NSTRIP 74
#define NBLK (2*NSTRIP)
#define TPB 640
#define SRC_I 30
#define DET_I 370
#define PI_F 3.14159265358979323846f
// exchange buffer: [parity][side][blk][jq 0..99][slot 0..7], float4 slots
#define EX_PP (2*NBLK*800)     // float4s per parity copy
#define NEX (2*EX_PP)

// Persistent device state (no allocations allowed)
__device__ float d_ie[NC];
__device__ float d_damp1[NX];
__device__ float4 d_ex[NEX];

__device__ __forceinline__ float4 ld_vol_v4(const float4* p) {
    float4 v;
    asm volatile("ld.volatile.global.v4.f32 {%0,%1,%2,%3}, [%4];"
                 : "=f"(v.x), "=f"(v.y), "=f"(v.z), "=f"(v.w) : "l"(p) : "memory");
    return v;
}
__device__ __forceinline__ void st_vol_v4(float4* p, float4 v) {
    asm volatile("st.volatile.global.v4.f32 [%0], {%1,%2,%3,%4};"
                 :: "l"(p), "f"(v.x), "f"(v.y), "f"(v.z), "f"(v.w) : "memory");
}

// try one poll pass of the 8 own slots + 3 neighbor-thread slots; extract on success
__device__ __forceinline__ bool poll_try(const float4* b, int jq, float thr,
    float4& e1, float4& e2, float4& hyv, float4& hxv, float& rX, float& lE, float& lHX)
{
    float4 a0 = ld_vol_v4(b+0), a1 = ld_vol_v4(b+1), a2 = ld_vol_v4(b+2), a3 = ld_vol_v4(b+3);
    float4 a4 = ld_vol_v4(b+4), a5 = ld_vol_v4(b+5), a6 = ld_vol_v4(b+6), a7 = ld_vol_v4(b+7);
    bool ok = a0.x>=thr && a0.w>=thr && a1.x>=thr && a1.w>=thr
           && a2.x>=thr && a2.w>=thr && a3.x>=thr && a3.w>=thr
           && a4.x>=thr && a4.w>=thr && a5.x>=thr && a5.w>=thr
           && a6.x>=thr && a6.w>=thr && a7.x>=thr && a7.w>=thr;
    float4 r0 = a0, l1 = a1, l7 = a7;
    if (jq < 99) { r0 = ld_vol_v4(b + 8);  ok = ok && r0.x>=thr && r0.w>=thr; }
    if (jq > 0)  { l1 = ld_vol_v4(b - 7); l7 = ld_vol_v4(b - 1);
                   ok = ok && l1.x>=thr && l1.w>=thr && l7.x>=thr && l7.w>=thr; }
    e1  = make_float4(a0.y, a0.z, a1.y, a1.z);
    e2  = make_float4(a2.y, a2.z, a3.y, a3.z);
    hyv = make_float4(a4.y, a4.z, a5.y, a5.z);
    hxv = make_float4(a6.y, a6.z, a7.y, a7.z);
    rX  = (jq < 99) ? r0.y : e1.w;
    lE  = (jq > 0)  ? l1.z : 0.f;
    lHX = (jq > 0)  ? l7.z : 0.f;
    return ok;
}

// ---------------- setup: eps, damp, zero exchange buffers ----------------
__global__ void setup_kernel(const float* __restrict__ radius) {
    int idx = blockIdx.x * blockDim.x + threadIdx.x;
    if (idx < NEX) d_ex[idx] = make_float4(0.f, 0.f, 0.f, 0.f);   // tag 0 = state at t=0
    if (idx < NX) {
        float v = 1.0f;
        if (idx < 10) {
            float rr = (10 - idx - 0.5f) * 0.1f;
            v = expf(-0.5f * rr * rr * rr);
        } else if (idx >= NX - 10) {
            float rr = (10 - (NX - 1 - idx) - 0.5f) * 0.1f;
            v = expf(-0.5f * rr * rr * rr);
        }
        d_damp1[idx] = v;
    }
    if (idx >= NC) return;
    int i = idx / NY;
    int j = idx - i * NY;
    int p   = (j + 10) / 80 - 1;
    int off = (j + 10) - 80 * (p + 1);
    bool inport = (p >= 0 && p < 4 && off < 20);
    float eps = 1.0f;
    if ((i < SRC_I || i >= DET_I) && inport) eps = 2.8f;
    if (i >= 80 && i < 320 && j >= 80 && j < 320) {
        int X = i - 80, Y = j - 80;
        int a = X / 30, b = Y / 30;
        float r = radius[a * 8 + b];
        if (r < 0.3f) r = 0.0f;
        float dx = (float)(X - (15 + 30 * a));
        float dy = (float)(Y - (15 + 30 * b));
        eps = (dx * dx + dy * dy <= r * r) ? 1.0f : 2.8f;
    }
    d_ie[idx] = 0.5f / eps;
}

// ---------- persistent strip kernel: lag-2 temporal blocking ----------
__global__ void __launch_bounds__(TPB, 1)
fdtd_kernel(const float* __restrict__ phases, float* __restrict__ out)
{
    __shared__ float sEz[2*6*NY];

    const int bk    = blockIdx.x;
    const int batch = bk / NSTRIP;
    const int s     = bk - batch * NSTRIP;
    const int r0    = (s * NX) / NSTRIP;
    const int r1    = ((s + 1) * NX) / NSTRIP;
    const int h     = r1 - r0;
    const bool hasA = (s > 0);
    const bool hasB = (s < NSTRIP - 1);
    const int tid   = threadIdx.x;
    const int bkA   = hasA ? bk - 1 : bk;
    const int bkB   = hasB ? bk + 1 : bk;

    const int  l    = tid / 100;
    const int  jq   = tid - l * 100;
    const bool act  = (tid < h * 100);
    const int  i    = r0 + l;
    const int  j0   = jq * 4;
    const int  o    = l * NY + j0;
    const bool spinA = act && (l == 0) && hasA;
    const bool spinB = act && (l == h - 1) && hasB;
    const bool pubT0 = spinA;                         // l==0 publishes E1/HY/HX upward
    const bool pubT1 = act && (l == 1) && hasA;       // E2 upward
    const bool pubB0 = spinB;                         // E1/HX downward
    const bool pubB1 = act && (l == h - 2) && hasB;   // E2/HY downward
    const bool upReg = act && (l > 0);
    const bool dnReg = act && (l < h - 1);
    const bool edgeTop = act && (l == 0) && !hasA;
    const bool edgeL   = (jq == 0);

    for (int x = tid; x < 2*6*NY; x += TPB) sEz[x] = 0.f;

    // exchange pointers (parity 0 base; add pp*EX_PP per use)
    const float4* cA = d_ex + ((size_t)(0*NBLK + bkA))*800 + jq*8;  // side0 of above
    const float4* cB = d_ex + ((size_t)(1*NBLK + bkB))*800 + jq*8;  // side1 of below
    float4*       pT = d_ex + ((size_t)(1*NBLK + bk ))*800 + jq*8;  // own side1 (for above)
    float4*       pB = d_ex + ((size_t)(0*NBLK + bk ))*800 + jq*8;  // own side0 (for below)

    // per-thread state
    float4 ez = {0,0,0,0}, hx = {0,0,0,0}, hy = {0,0,0,0}, hyU = {0,0,0,0};
    float4 ezH = {0,0,0,0};                      // redundant halo Ez row (boundary threads)
    float4 dmp = {0,0,0,0}, iek = {0,0,0,0}, ieH = {0,0,0,0};
    float  hxW = 0.f, rU = 1.f, rL = 1.f, rH2 = 1.f, rHB = 1.f, dHL = 0.f;
    float4 Ssin = {0,0,0,0}, Scos = {0,0,0,0};
    bool hasSrc = false, hasDet = false;

    if (act) {
        float di = d_damp1[i];
        dmp.x = di * d_damp1[j0];   dmp.y = di * d_damp1[j0+1];
        dmp.z = di * d_damp1[j0+2]; dmp.w = di * d_damp1[j0+3];
        iek = *(const float4*)&d_ie[i * NY + j0];
        if (i > 0)  rU = d_damp1[i - 1] / di;
        if (j0 > 0) rL = d_damp1[j0 - 1] / d_damp1[j0];
        if (spinA) {
            int rowH = r0 - 1;
            rH2 = d_damp1[r0 - 2] / di;
            ieH = *(const float4*)&d_ie[rowH * NY + j0];
            if (jq > 0) dHL = d_damp1[rowH] * d_damp1[j0 - 1];
        }
        if (spinB) {
            int rowH = r1;
            rHB = d_damp1[r1] / di;
            ieH = *(const float4*)&d_ie[rowH * NY + j0];
            if (jq > 0) dHL = d_damp1[rowH] * d_damp1[j0 - 1];
        }
        if (i == SRC_I || i == DET_I) {
            float* ss = &Ssin.x; float* sc = &Scos.x;
            #pragma unroll
            for (int c = 0; c < 4; ++c) {
                int j = j0 + c;
                int p = (j + 10) / 80 - 1;
                int o2 = (j + 10) - 80 * (p + 1);
                bool inport = (p >= 0 && p < 4 && o2 < 20);
                if (inport && i == SRC_I) {
                    float ps = PI_F * phases[batch * 4 + p];
                    ss[c] = sinf(ps); sc[c] = cosf(ps);
                    hasSrc = true;
                }
                if (inport && i == DET_I) hasDet = true;
            }
        }
    }
    const float W  = (float)(2.0 * 3.14159265358979323846 * (12.5 / 1550.0));
    const float cW = cosf(W), sW = sinf(W);
    __syncthreads();

    float* buf0 = sEz;
    float* buf1 = sEz + 6*NY;

    for (int m = 0; m < STEPS/2; ++m) {
        const int ppoll = m & 1;
        const int ppub  = (m + 1) & 1;
        const float thr = (float)(2*m);
        const float tg  = (float)(2*m + 2);

        // ================= ODD step t = 2m+1: poll + compute + halo Ez =================
        {
            float ezL = ez.x, ezE = ez.w;
            float4 ezUq = ez, ezDq = ez;
            if (act) {
                if (!edgeL)  ezL  = buf0[o - 1];
                if (jq < 99) ezE  = buf0[o + 4];
                if (upReg)   ezUq = *(const float4*)&buf0[o - NY];
                if (dnReg)   ezDq = *(const float4*)&buf0[o + NY];
            }
            float4 rE1={0,0,0,0}, rE2={0,0,0,0}, rHY={0,0,0,0}, rHX={0,0,0,0};
            float  rXX=0.f, rLE=0.f, rLHX=0.f;
            float4 hyH2={0,0,0,0}, hxH={0,0,0,0}, hyB={0,0,0,0}, hxB={0,0,0,0};
            float  hxHL=0.f, hxBL=0.f;

            if (spinA) {
                const float4* b = cA + ppoll*EX_PP;
                while (!poll_try(b, jq, thr, rE1, rE2, rHY, rHX, rXX, rLE, rLHX)) {}
                ezUq = rE1;
                // Hy at row r0-2 (time t)
                hyH2.x = rH2*dmp.x*(rHY.x + 0.5f*(rE1.x - rE2.x));
                hyH2.y = rH2*dmp.y*(rHY.y + 0.5f*(rE1.y - rE2.y));
                hyH2.z = rH2*dmp.z*(rHY.z + 0.5f*(rE1.z - rE2.z));
                hyH2.w = rH2*dmp.w*(rHY.w + 0.5f*(rE1.w - rE2.w));
                // Hx at row r0-1 (time t)
                hxH.x = rU*dmp.x*(rHX.x - 0.5f*(rE1.y - rE1.x));
                hxH.y = rU*dmp.y*(rHX.y - 0.5f*(rE1.z - rE1.y));
                hxH.z = rU*dmp.z*(rHX.z - 0.5f*(rE1.w - rE1.z));
                hxH.w = rU*dmp.w*(rHX.w - 0.5f*(rXX   - rE1.w));
                hxHL  = (jq > 0) ? dHL*(rLHX - 0.5f*(rE1.x - rLE)) : hxH.x;
            }
            if (spinB) {
                const float4* b = cB + ppoll*EX_PP;
                while (!poll_try(b, jq, thr, rE1, rE2, rHY, rHX, rXX, rLE, rLHX)) {}
                ezDq = rE1;
                // Hy at row r1 (time t)
                hyB.x = rHB*dmp.x*(rHY.x + 0.5f*(rE2.x - rE1.x));
                hyB.y = rHB*dmp.y*(rHY.y + 0.5f*(rE2.y - rE1.y));
                hyB.z = rHB*dmp.z*(rHY.z + 0.5f*(rE2.z - rE1.z));
                hyB.w = rHB*dmp.w*(rHY.w + 0.5f*(rE2.w - rE1.w));
                // Hx at row r1 (time t)
                hxB.x = rHB*dmp.x*(rHX.x - 0.5f*(rE1.y - rE1.x));
                hxB.y = rHB*dmp.y*(rHX.y - 0.5f*(rE1.z - rE1.y));
                hxB.z = rHB*dmp.z*(rHX.z - 0.5f*(rE1.w - rE1.z));
                hxB.w = rHB*dmp.w*(rHX.w - 0.5f*(rXX   - rE1.w));
                hxBL  = (jq > 0) ? dHL*(rLHX - 0.5f*(rE1.x - rLE)) : hxB.x;
            }

            if (act) {
                // hyU recurrence (Hy of row above)
                hyU.x = rU*dmp.x*(hyU.x + 0.5f*(ez.x - ezUq.x));
                hyU.y = rU*dmp.y*(hyU.y + 0.5f*(ez.y - ezUq.y));
                hyU.z = rU*dmp.z*(hyU.z + 0.5f*(ez.z - ezUq.z));
                hyU.w = rU*dmp.w*(hyU.w + 0.5f*(ez.w - ezUq.w));
                // own H
                hx.x = dmp.x*(hx.x - 0.5f*(ez.y - ez.x));
                hx.y = dmp.y*(hx.y - 0.5f*(ez.z - ez.y));
                hx.z = dmp.z*(hx.z - 0.5f*(ez.w - ez.z));
                hx.w = dmp.w*(hx.w - 0.5f*(ezE  - ez.w));
                hy.x = dmp.x*(hy.x + 0.5f*(ezDq.x - ez.x));
                hy.y = dmp.y*(hy.y + 0.5f*(ezDq.y - ez.y));
                hy.z = dmp.z*(hy.z + 0.5f*(ezDq.z - ez.z));
                hy.w = dmp.w*(hy.w + 0.5f*(ezDq.w - ez.w));
                hxW  = rL*dmp.x*(hxW - 0.5f*(ez.x - ezL));
                // own E
                float4 hyUe = edgeTop ? hy : hyU;
                float  hxWe = edgeL   ? hx.x : hxW;
                ez.x = dmp.x*(ez.x + iek.x*((hy.x - hyUe.x) - (hx.x - hxWe)));
                ez.y = dmp.y*(ez.y + iek.y*((hy.y - hyUe.y) - (hx.y - hx.x)));
                ez.z = dmp.z*(ez.z + iek.z*((hy.z - hyUe.z) - (hx.z - hx.y)));
                ez.w = dmp.w*(ez.w + iek.w*((hy.w - hyUe.w) - (hx.w - hx.z)));
                if (hasSrc) {
                    ez.x += Ssin.x; ez.y += Ssin.y; ez.z += Ssin.z; ez.w += Ssin.w;
                    float ns, nc;
                    ns = Ssin.x*cW + Scos.x*sW; nc = Scos.x*cW - Ssin.x*sW; Ssin.x = ns; Scos.x = nc;
                    ns = Ssin.y*cW + Scos.y*sW; nc = Scos.y*cW - Ssin.y*sW; Ssin.y = ns; Scos.y = nc;
                    ns = Ssin.z*cW + Scos.z*sW; nc = Scos.z*cW - Ssin.z*sW; Ssin.z = ns; Scos.z = nc;
                    ns = Ssin.w*cW + Scos.w*sW; nc = Scos.w*cW - Ssin.w*sW; Ssin.w = ns; Scos.w = nc;
                }
                // halo Ez row (time t), computed redundantly
                if (spinA) {   // row r0-1
                    ezH.x = rU*dmp.x*(rE1.x + ieH.x*((hyU.x - hyH2.x) - (hxH.x - hxHL)));
                    ezH.y = rU*dmp.y*(rE1.y + ieH.y*((hyU.y - hyH2.y) - (hxH.y - hxH.x)));
                    ezH.z = rU*dmp.z*(rE1.z + ieH.z*((hyU.z - hyH2.z) - (hxH.z - hxH.y)));
                    ezH.w = rU*dmp.w*(rE1.w + ieH.w*((hyU.w - hyH2.w) - (hxH.w - hxH.z)));
                }
                if (spinB) {   // row r1
                    ezH.x = rHB*dmp.x*(rE1.x + ieH.x*((hyB.x - hy.x) - (hxB.x - hxBL)));
                    ezH.y = rHB*dmp.y*(rE1.y + ieH.y*((hyB.y - hy.y) - (hxB.y - hxB.x)));
                    ezH.z = rHB*dmp.z*(rE1.z + ieH.z*((hyB.z - hy.z) - (hxB.z - hxB.y)));
                    ezH.w = rHB*dmp.w*(rE1.w + ieH.w*((hyB.w - hy.w) - (hxB.w - hxB.z)));
                }
                *(float4*)&buf1[o] = ez;
            }
            __syncthreads();
        }

        // ================= EVEN step t = 2m+2: compute + publish =================
        {
            float ezL = ez.x, ezE = ez.w;
            float4 ezUq = ez, ezDq = ez;
            if (act) {
                if (!edgeL)  ezL  = buf1[o - 1];
                if (jq < 99) ezE  = buf1[o + 4];
                if (upReg)   ezUq = *(const float4*)&buf1[o - NY];
                if (dnReg)   ezDq = *(const float4*)&buf1[o + NY];
            }
            if (spinA) ezUq = ezH;     // halo Ez(t-1) computed locally
            if (spinB) ezDq = ezH;

            if (act) {
                hyU.x = rU*dmp.x*(hyU.x + 0.5f*(ez.x - ezUq.x));
                hyU.y = rU*dmp.y*(hyU.y + 0.5f*(ez.y - ezUq.y));
                hyU.z = rU*dmp.z*(hyU.z + 0.5f*(ez.z - ezUq.z));
                hyU.w = rU*dmp.w*(hyU.w + 0.5f*(ez.w - ezUq.w));
                hx.x = dmp.x*(hx.x - 0.5f*(ez.y - ez.x));
                hx.y = dmp.y*(hx.y - 0.5f*(ez.z - ez.y));
                hx.z = dmp.z*(hx.z - 0.5f*(ez.w - ez.z));
                hx.w = dmp.w*(hx.w - 0.5f*(ezE  - ez.w));
                hy.x = dmp.x*(hy.x + 0.5f*(ezDq.x - ez.x));
                hy.y = dmp.y*(hy.y + 0.5f*(ezDq.y - ez.y));
                hy.z = dmp.z*(hy.z + 0.5f*(ezDq.z - ez.z));
                hy.w = dmp.w*(hy.w + 0.5f*(ezDq.w - ez.w));
                hxW  = rL*dmp.x*(hxW - 0.5f*(ez.x - ezL));
                float4 hyUe = edgeTop ? hy : hyU;
                float  hxWe = edgeL   ? hx.x : hxW;
                ez.x = dmp.x*(ez.x + iek.x*((hy.x - hyUe.x) - (hx.x - hxWe)));
                ez.y = dmp.y*(ez.y + iek.y*((hy.y - hyUe.y) - (hx.y - hx.x)));
                ez.z = dmp.z*(ez.z + iek.z*((hy.z - hyUe.z) - (hx.z - hx.y)));
                ez.w = dmp.w*(ez.w + iek.w*((hy.w - hyUe.w) - (hx.w - hx.z)));
                if (hasSrc) {
                    ez.x += Ssin.x; ez.y += Ssin.y; ez.z += Ssin.z; ez.w += Ssin.w;
                    float ns, nc;
                    ns = Ssin.x*cW + Scos.x*sW; nc = Scos.x*cW - Ssin.x*sW; Ssin.x = ns; Scos.x = nc;
                    ns = Ssin.y*cW + Scos.y*sW; nc = Scos.y*cW - Ssin.y*sW; Ssin.y = ns; Scos.y = nc;
                    ns = Ssin.z*cW + Scos.z*sW; nc = Scos.z*cW - Ssin.z*sW; Ssin.z = ns; Scos.z = nc;
                    ns = Ssin.w*cW + Scos.w*sW; nc = Scos.w*cW - Ssin.w*sW; Ssin.w = ns; Scos.w = nc;
                }

                // publish time-t boundary state for the next 2 consumer steps
                if (m != STEPS/2 - 1) {
                    if (pubT0) {
                        float4* b = pT + ppub*EX_PP;
                        st_vol_v4(b+0, make_float4(tg, ez.x, ez.y, tg));
                        st_vol_v4(b+1, make_float4(tg, ez.z, ez.w, tg));
                        st_vol_v4(b+4, make_float4(tg, hy.x, hy.y, tg));
                        st_vol_v4(b+5, make_float4(tg, hy.z, hy.w, tg));
                        st_vol_v4(b+6, make_float4(tg, hx.x, hx.y, tg));
                        st_vol_v4(b+7, make_float4(tg, hx.z, hx.w, tg));
                    }
                    if (pubT1) {
                        float4* b = pT + ppub*EX_PP;
                        st_vol_v4(b+2, make_float4(tg, ez.x, ez.y, tg));
                        st_vol_v4(b+3, make_float4(tg, ez.z, ez.w, tg));
                    }
                    if (pubB0) {
                        float4* b = pB + ppub*EX_PP;
                        st_vol_v4(b+0, make_float4(tg, ez.x, ez.y, tg));
                        st_vol_v4(b+1, make_float4(tg, ez.z, ez.w, tg));
                        st_vol_v4(b+6, make_float4(tg, hx.x, hx.y, tg));
                        st_vol_v4(b+7, make_float4(tg, hx.z, hx.w, tg));
                    }
                    if (pubB1) {
                        float4* b = pB + ppub*EX_PP;
                        st_vol_v4(b+2, make_float4(tg, ez.x, ez.y, tg));
                        st_vol_v4(b+3, make_float4(tg, ez.z, ez.w, tg));
                        st_vol_v4(b+4, make_float4(tg, hy.x, hy.y, tg));
                        st_vol_v4(b+5, make_float4(tg, hy.z, hy.w, tg));
                    }
                }
                *(float4*)&buf0[o] = ez;
            }
            __syncthreads();
        }
    }

    // ---- detector: final Ez at row 370 lives in registers ----
    if (hasDet) {
        const float* ec = &ez.x;
        #pragma unroll
        for (int c = 0; c < 4; ++c) {
            int j = j0 + c;
            int p = (j + 10) / 80 - 1;
            int o2 = (j + 10) - 80 * (p + 1);
            if (p >= 0 && p < 4 && o2 < 20)
                out[batch * 80 + p * 20 + o2] = ec[c];
        }
    }
}

extern "C" void kernel_launch(void* const* d_in, const int* in_sizes, int n_in,
                              void* d_out, int out_size) {
    const float* phases = (const float*)d_in[0];   // (2,4)
    const float* radius = (const float*)d_in[1];   // (8,8)
    float* out = (float*)d_out;                    // (2,4,20)
    setup_kernel<<<(NEX + 255) / 256, 256>>>(radius);
    fdtd_kernel<<<NBLK, TPB>>>(phases, out);
}

// round 10
// speedup vs baseline: 3.5839x; 3.5839x over previous
#include <cuda_runtime.h>
#include <math.h>

#define NX 400
#define NY 400
#define NC (NX*NY)
#define STEPS 300
#define NSTRIP 74
#define NBLK (2*NSTRIP)
#define TPB 640
#define SRC_I 30
#define DET_I 370
#define PI_F 3.14159265358979323846f
#define NSLOT 200                  // 2 columns per 16B slot

// Persistent device state (no allocations allowed)
__device__ float d_ie[NC];                 // COURANT / eps
__device__ float d_damp1[NX];              // 1-D damp profile (x == y)
__device__ float4 d_slT[2*NBLK*NSLOT];     // [parity][blk][slot]: top-row Ez, tag-fused
__device__ float4 d_slB[2*NBLK*NSLOT];     // bottom-row Ez, tag-fused

// GPU-scope relaxed 16B exchange ops (stay in L2; avoid SYS-scope coherence path)
__device__ __forceinline__ float4 ld_gpu_v4(const float4* p) {
    float4 v;
    asm volatile("ld.relaxed.gpu.global.v4.f32 {%0,%1,%2,%3}, [%4];"
                 : "=f"(v.x), "=f"(v.y), "=f"(v.z), "=f"(v.w) : "l"(p) : "memory");
    return v;
}
__device__ __forceinline__ void st_gpu_v4(float4* p, float4 v) {
    asm volatile("st.relaxed.gpu.global.v4.f32 [%0], {%1,%2,%3,%4};"
                 :: "l"(p), "f"(v.x), "f"(v.y), "f"(v.z), "f"(v.w) : "memory");
}

// ---------------- setup: eps, damp, zero slot buffers ----------------
__global__ void setup_kernel(const float* __restrict__ radius) {
    int idx = blockIdx.x * blockDim.x + threadIdx.x;
    if (idx < 2*NBLK*NSLOT) {
        d_slT[idx] = make_float4(0.f, 0.f, 0.f, 0.f);   // tag 0 == "step 0 published", Ez=0
        d_slB[idx] = make_float4(0.f, 0.f, 0.f, 0.f);
    }
    if (idx < NX) {
        float v = 1.0f;
        if (idx < 10) {
            float rr = (10 - idx - 0.5f) * 0.1f;
            v = expf(-0.5f * rr * rr * rr);
        } else if (idx >= NX - 10) {
            float rr = (10 - (NX - 1 - idx) - 0.5f) * 0.1f;
            v = expf(-0.5f * rr * rr * rr);
        }
        d_damp1[idx] = v;
    }
    if (idx >= NC) return;
    int i = idx / NY;
    int j = idx - i * NY;
    int p   = (j + 10) / 80 - 1;
    int off = (j + 10) - 80 * (p + 1);
    bool inport = (p >= 0 && p < 4 && off < 20);
    float eps = 1.0f;
    if ((i < SRC_I || i >= DET_I) && inport) eps = 2.8f;
    if (i >= 80 && i < 320 && j >= 80 && j < 320) {
        int X = i - 80, Y = j - 80;
        int a = X / 30, b = Y / 30;
        float r = radius[a * 8 + b];
        if (r < 0.3f) r = 0.0f;
        float dx = (float)(X - (15 + 30 * a));
        float dy = (float)(Y - (15 + 30 * b));
        eps = (dx * dx + dy * dy <= r * r) ? 1.0f : 2.8f;
    }
    d_ie[idx] = 0.5f / eps;
}

// ---------- persistent strip kernel: quads, register halos, tag-fused exchange ----------
__global__ void __launch_bounds__(TPB, 1)
fdtd_kernel(const float* __restrict__ phases, float* __restrict__ out)
{
    __shared__ float sEz[2*6*NY];     // parity double-buffered Ez of own strip rows

    const int bk    = blockIdx.x;
    const int batch = bk / NSTRIP;
    const int s     = bk - batch * NSTRIP;
    const int r0    = (s * NX) / NSTRIP;
    const int r1    = ((s + 1) * NX) / NSTRIP;
    const int h     = r1 - r0;
    const bool hasA = (s > 0);
    const bool hasB = (s < NSTRIP - 1);
    const int tid   = threadIdx.x;
    const int bkA   = hasA ? bk - 1 : bk;
    const int bkB   = hasB ? bk + 1 : bk;

    const int  l    = tid / 100;
    const int  jq   = tid - l * 100;
    const bool act  = (tid < h * 100);
    const int  i    = r0 + l;
    const int  j0   = jq * 4;
    const int  o    = l * NY + j0;
    const bool topT = act && (l == 0);
    const bool botT = act && (l == h - 1);
    const bool spinA = topT && hasA;
    const bool spinB = botT && hasB;
    const bool upReg  = act && (l > 0);       // up Ez quad comes from smem
    const bool dnReg  = act && (l < h - 1);   // down Ez quad comes from smem

    for (int x = tid; x < 2*6*NY; x += TPB) sEz[x] = 0.f;

    // tag-fused slot pointers (parity offset added per step)
    const float4* plA = d_slB + bkA*NSLOT + 2*jq;   // above's bottom Ez slots
    const float4* plB = d_slT + bkB*NSLOT + 2*jq;   // below's top Ez slots
    float4*       psT = d_slT + bk*NSLOT + 2*jq;    // own top publish
    float4*       psB = d_slB + bk*NSLOT + 2*jq;    // own bottom publish

    // per-thread state
    float4 ez = {0,0,0,0}, hx = {0,0,0,0}, hy = {0,0,0,0}, hyU = {0,0,0,0};
    float4 dmp = {0,0,0,0}, iek = {0,0,0,0};
    float  hxW = 0.f, rU = 1.f, rL = 1.f;      // damp ratios for halo rows
    float4 Ssin = {0,0,0,0}, Scos = {0,0,0,0};
    bool hasSrc = false, hasDet = false;
    const bool edgeTop = topT && !hasA;        // global i==0
    const bool edgeL   = (jq == 0);

    if (act) {
        float di = d_damp1[i];
        dmp.x = di * d_damp1[j0];   dmp.y = di * d_damp1[j0+1];
        dmp.z = di * d_damp1[j0+2]; dmp.w = di * d_damp1[j0+3];
        iek = *(const float4*)&d_ie[i * NY + j0];
        if (i > 0)  rU = d_damp1[i - 1] / di;
        if (j0 > 0) rL = d_damp1[j0 - 1] / d_damp1[j0];
        if (i == SRC_I || i == DET_I) {
            float* ss = &Ssin.x; float* sc = &Scos.x;
            #pragma unroll
            for (int c = 0; c < 4; ++c) {
                int j = j0 + c;
                int p = (j + 10) / 80 - 1;
                int o2 = (j + 10) - 80 * (p + 1);
                bool inport = (p >= 0 && p < 4 && o2 < 20);
                if (inport && i == SRC_I) {
                    float ps = PI_F * phases[batch * 4 + p];
                    ss[c] = sinf(ps);     // angle at t=1 (tf=0)
                    sc[c] = cosf(ps);
                    hasSrc = true;
                }
                if (inport && i == DET_I) hasDet = true;
            }
        }
    }
    const float W  = (float)(2.0 * 3.14159265358979323846 * (12.5 / 1550.0));
    const float cW = cosf(W), sW = sinf(W);
    __syncthreads();

    for (unsigned t = 1; t <= STEPS; ++t) {
        const int qo = (int)((t - 1) & 1u) * (NBLK*NSLOT);
        const int po = (int)(t & 1u) * (NBLK*NSLOT);
        const float tf1  = (float)(t - 1);    // tag we need from neighbors
        const float tagf = (float)t;          // tag we publish
        const float* bufQ = sEz + (int)((t - 1) & 1u) * (6*NY);
        float*       bufP = sEz + (int)(t & 1u) * (6*NY);

        // ---- issue first poll attempt ASAP (longest-latency loads first) ----
        float4 a0, a1, b0, b1;
        if (spinA) { a0 = ld_gpu_v4(plA + qo); a1 = ld_gpu_v4(plA + qo + 1); }
        if (spinB) { b0 = ld_gpu_v4(plB + qo); b1 = ld_gpu_v4(plB + qo + 1); }

        // ---- gather Ez(t-1) neighbors from smem (overlaps the poll loads) ----
        float  ezL = ez.x, ezE = ez.w;
        float4 ezU = ez,   ezD = ez;
        if (act) {
            if (!edgeL)   ezL = bufQ[o - 1];
            if (jq < 99)  ezE = bufQ[o + 4];
            if (upReg)    ezU = *(const float4*)&bufQ[o - NY];
            if (dnReg)    ezD = *(const float4*)&bufQ[o + NY];
        }
        if (spinA) {                 // poll tag-fused slots: data arrives with the tag
            while (a0.x < tf1 || a0.w < tf1 || a1.x < tf1 || a1.w < tf1) {
                a0 = ld_gpu_v4(plA + qo); a1 = ld_gpu_v4(plA + qo + 1);
            }
            ezU = make_float4(a0.y, a0.z, a1.y, a1.z);
        }
        if (spinB) {
            while (b0.x < tf1 || b0.w < tf1 || b1.x < tf1 || b1.w < tf1) {
                b0 = ld_gpu_v4(plB + qo); b1 = ld_gpu_v4(plB + qo + 1);
            }
            ezD = make_float4(b0.y, b0.z, b1.y, b1.z);
        }

        if (act) {
            // ---- halo H recurrences (use Ez(t-1)) ----
            hyU.x = rU * dmp.x * (hyU.x + 0.5f * (ez.x - ezU.x));
            hyU.y = rU * dmp.y * (hyU.y + 0.5f * (ez.y - ezU.y));
            hyU.z = rU * dmp.z * (hyU.z + 0.5f * (ez.z - ezU.z));
            hyU.w = rU * dmp.w * (hyU.w + 0.5f * (ez.w - ezU.w));
            hxW   = rL * dmp.x * (hxW   - 0.5f * (ez.x - ezL));

            // ---- own H ----
            hx.x = dmp.x * (hx.x - 0.5f * (ez.y - ez.x));
            hx.y = dmp.y * (hx.y - 0.5f * (ez.z - ez.y));
            hx.z = dmp.z * (hx.z - 0.5f * (ez.w - ez.z));
            hx.w = dmp.w * (hx.w - 0.5f * (ezE  - ez.w));
            hy.x = dmp.x * (hy.x + 0.5f * (ezD.x - ez.x));
            hy.y = dmp.y * (hy.y + 0.5f * (ezD.y - ez.y));
            hy.z = dmp.z * (hy.z + 0.5f * (ezD.z - ez.z));
            hy.w = dmp.w * (hy.w + 0.5f * (ezD.w - ez.w));

            // ---- E: all registers ----
            float4 hyUe = edgeTop ? hy : hyU;      // i==0: dHy_x = 0
            float  hxWe = edgeL   ? hx.x : hxW;    // j==0: dHx_y = 0
            ez.x = dmp.x * (ez.x + iek.x * ((hy.x - hyUe.x) - (hx.x - hxWe)));
            ez.y = dmp.y * (ez.y + iek.y * ((hy.y - hyUe.y) - (hx.y - hx.x)));
            ez.z = dmp.z * (ez.z + iek.z * ((hy.z - hyUe.z) - (hx.z - hx.y)));
            ez.w = dmp.w * (ez.w + iek.w * ((hy.w - hyUe.w) - (hx.w - hx.z)));

            if (hasSrc) {
                ez.x += Ssin.x;  ez.y += Ssin.y;  ez.z += Ssin.z;  ez.w += Ssin.w;
                float ns, nc;
                ns = Ssin.x * cW + Scos.x * sW; nc = Scos.x * cW - Ssin.x * sW; Ssin.x = ns; Scos.x = nc;
                ns = Ssin.y * cW + Scos.y * sW; nc = Scos.y * cW - Ssin.y * sW; Ssin.y = ns; Scos.y = nc;
                ns = Ssin.z * cW + Scos.z * sW; nc = Scos.z * cW - Ssin.z * sW; Ssin.z = ns; Scos.z = nc;
                ns = Ssin.w * cW + Scos.w * sW; nc = Scos.w * cW - Ssin.w * sW; Ssin.w = ns; Scos.w = nc;
            }

            // ---- publish boundary quads ASAP ----
            // Ordering: publish payload is data-dependent on this thread's poll
            // (poll -> hyU -> ez), and the WAR on the parity slot is covered by the
            // protocol (observing neighbor's t-1 tag implies it consumed our t-2 slot).
            if (topT) {
                st_gpu_v4(psT + po,     make_float4(tagf, ez.x, ez.y, tagf));
                st_gpu_v4(psT + po + 1, make_float4(tagf, ez.z, ez.w, tagf));
            }
            if (botT) {
                st_gpu_v4(psB + po,     make_float4(tagf, ez.x, ez.y, tagf));
                st_gpu_v4(psB + po + 1, make_float4(tagf, ez.z, ez.w, tagf));
            }
            *(float4*)&bufP[o] = ez;
        }
        __syncthreads();
    }

    // ---- detector: final Ez at row 370 lives in registers ----
    if (hasDet) {
        const float* ec = &ez.x;
        #pragma unroll
        for (int c = 0; c < 4; ++c) {
            int j = j0 + c;
            int p = (j + 10) / 80 - 1;
            int o2 = (j + 10) - 80 * (p + 1);
            if (p >= 0 && p < 4 && o2 < 20)
                out[batch * 80 + p * 20 + o2] = ec[c];
        }
    }
}

extern "C" void kernel_launch(void* const* d_in, const int* in_sizes, int n_in,
                              void* d_out, int out_size) {
    const float* phases = (const float*)d_in[0];   // (2,4)
    const float* radius = (const float*)d_in[1];   // (8,8)
    float* out = (float*)d_out;                    // (2,4,20)
    setup_kernel<<<(NC + 255) / 256, 256>>>(radius);
    fdtd_kernel<<<NBLK, TPB>>>(phases, out);
}

// round 11
// speedup vs baseline: 4.7844x; 1.3350x over previous
#include <cuda_runtime.h>
#include <math.h>

#define NX 400
#define NY 400
#define NC (NX*NY)
#define STEPS 300
#define NSTRIP 74
#define NBLK (2*NSTRIP)
#define TPB 640
#define SRC_I 30
#define DET_I 370
#define PI_F 3.14159265358979323846f
#define NSLOT 200                  // 2 columns per 16B slot

// Persistent device state (no allocations allowed)
__device__ float d_ie[NC];                 // COURANT / eps
__device__ float d_damp1[NX];              // 1-D damp profile (x == y)
__device__ float4 d_slT[2*NBLK*NSLOT];     // [parity][blk][slot]: top-row Ez, tag-fused
__device__ float4 d_slB[2*NBLK*NSLOT];     // bottom-row Ez, tag-fused

// GPU-scope relaxed 16B exchange ops (stay in L2)
__device__ __forceinline__ float4 ld_gpu_v4(const float4* p) {
    float4 v;
    asm volatile("ld.relaxed.gpu.global.v4.f32 {%0,%1,%2,%3}, [%4];"
                 : "=f"(v.x), "=f"(v.y), "=f"(v.z), "=f"(v.w) : "l"(p) : "memory");
    return v;
}
__device__ __forceinline__ void st_gpu_v4(float4* p, float4 v) {
    asm volatile("st.relaxed.gpu.global.v4.f32 [%0], {%1,%2,%3,%4};"
                 :: "l"(p), "f"(v.x), "f"(v.y), "f"(v.z), "f"(v.w) : "memory");
}

// ---------------- setup: eps, damp, zero slot buffers ----------------
__global__ void setup_kernel(const float* __restrict__ radius) {
    int idx = blockIdx.x * blockDim.x + threadIdx.x;
    if (idx < 2*NBLK*NSLOT) {
        d_slT[idx] = make_float4(0.f, 0.f, 0.f, 0.f);   // tag 0 == "step 0 published", Ez=0
        d_slB[idx] = make_float4(0.f, 0.f, 0.f, 0.f);
    }
    if (idx < NX) {
        float v = 1.0f;
        if (idx < 10) {
            float rr = (10 - idx - 0.5f) * 0.1f;
            v = expf(-0.5f * rr * rr * rr);
        } else if (idx >= NX - 10) {
            float rr = (10 - (NX - 1 - idx) - 0.5f) * 0.1f;
            v = expf(-0.5f * rr * rr * rr);
        }
        d_damp1[idx] = v;
    }
    if (idx >= NC) return;
    int i = idx / NY;
    int j = idx - i * NY;
    int p   = (j + 10) / 80 - 1;
    int off = (j + 10) - 80 * (p + 1);
    bool inport = (p >= 0 && p < 4 && off < 20);
    float eps = 1.0f;
    if ((i < SRC_I || i >= DET_I) && inport) eps = 2.8f;
    if (i >= 80 && i < 320 && j >= 80 && j < 320) {
        int X = i - 80, Y = j - 80;
        int a = X / 30, b = Y / 30;
        float r = radius[a * 8 + b];
        if (r < 0.3f) r = 0.0f;
        float dx = (float)(X - (15 + 30 * a));
        float dy = (float)(Y - (15 + 30 * b));
        eps = (dx * dx + dy * dy <= r * r) ? 1.0f : 2.8f;
    }
    d_ie[idx] = 0.5f / eps;
}

// ---------- persistent strip kernel: quads, register halos, prefetched tag-fused exchange ----------
__global__ void __launch_bounds__(TPB, 1)
fdtd_kernel(const float* __restrict__ phases, float* __restrict__ out)
{
    __shared__ float sEz[2*6*NY];     // parity double-buffered Ez of own strip rows

    const int bk    = blockIdx.x;
    const int batch = bk / NSTRIP;
    const int s     = bk - batch * NSTRIP;
    const int r0    = (s * NX) / NSTRIP;
    const int r1    = ((s + 1) * NX) / NSTRIP;
    const int h     = r1 - r0;
    const bool hasA = (s > 0);
    const bool hasB = (s < NSTRIP - 1);
    const int tid   = threadIdx.x;
    const int bkA   = hasA ? bk - 1 : bk;
    const int bkB   = hasB ? bk + 1 : bk;

    const int  l    = tid / 100;
    const int  jq   = tid - l * 100;
    const bool act  = (tid < h * 100);
    const int  i    = r0 + l;
    const int  j0   = jq * 4;
    const int  o    = l * NY + j0;
    const bool topT = act && (l == 0);
    const bool botT = act && (l == h - 1);
    const bool spinA = topT && hasA;
    const bool spinB = botT && hasB;
    const bool upReg  = act && (l > 0);
    const bool dnReg  = act && (l < h - 1);

    for (int x = tid; x < 2*6*NY; x += TPB) sEz[x] = 0.f;

    // tag-fused slot pointers (parity offset added per step)
    const float4* plA = d_slB + bkA*NSLOT + 2*jq;   // above's bottom Ez slots
    const float4* plB = d_slT + bkB*NSLOT + 2*jq;   // below's top Ez slots
    float4*       psT = d_slT + bk*NSLOT + 2*jq;    // own top publish
    float4*       psB = d_slB + bk*NSLOT + 2*jq;    // own bottom publish

    // per-thread state
    float4 ez = {0,0,0,0}, hx = {0,0,0,0}, hy = {0,0,0,0}, hyU = {0,0,0,0};
    float4 dmp = {0,0,0,0}, iek = {0,0,0,0};
    float  hxW = 0.f, rU = 1.f, rL = 1.f;
    float4 Ssin = {0,0,0,0}, Scos = {0,0,0,0};
    bool hasSrc = false, hasDet = false;
    const bool edgeTop = topT && !hasA;
    const bool edgeL   = (jq == 0);

    if (act) {
        float di = d_damp1[i];
        dmp.x = di * d_damp1[j0];   dmp.y = di * d_damp1[j0+1];
        dmp.z = di * d_damp1[j0+2]; dmp.w = di * d_damp1[j0+3];
        iek = *(const float4*)&d_ie[i * NY + j0];
        if (i > 0)  rU = d_damp1[i - 1] / di;
        if (j0 > 0) rL = d_damp1[j0 - 1] / d_damp1[j0];
        if (i == SRC_I || i == DET_I) {
            float* ss = &Ssin.x; float* sc = &Scos.x;
            #pragma unroll
            for (int c = 0; c < 4; ++c) {
                int j = j0 + c;
                int p = (j + 10) / 80 - 1;
                int o2 = (j + 10) - 80 * (p + 1);
                bool inport = (p >= 0 && p < 4 && o2 < 20);
                if (inport && i == SRC_I) {
                    float ps = PI_F * phases[batch * 4 + p];
                    ss[c] = sinf(ps);     // angle at t=1 (tf=0)
                    sc[c] = cosf(ps);
                    hasSrc = true;
                }
                if (inport && i == DET_I) hasDet = true;
            }
        }
    }
    const float W  = (float)(2.0 * 3.14159265358979323846 * (12.5 / 1550.0));
    const float cW = cosf(W), sW = sinf(W);
    __syncthreads();

    // prime the prefetch pipeline: loads for parity 0 (step 1 reads qo=0; init tags==0 are valid)
    float4 a0 = {0,0,0,0}, a1 = {0,0,0,0}, b0 = {0,0,0,0}, b1 = {0,0,0,0};
    if (spinA) { a0 = ld_gpu_v4(plA); a1 = ld_gpu_v4(plA + 1); }
    if (spinB) { b0 = ld_gpu_v4(plB); b1 = ld_gpu_v4(plB + 1); }

    for (unsigned t = 1; t <= STEPS; ++t) {
        const int qo = (int)((t - 1) & 1u) * (NBLK*NSLOT);
        const int po = (int)(t & 1u) * (NBLK*NSLOT);
        const float tf1  = (float)(t - 1);    // tag we need from neighbors
        const float tagf = (float)t;          // tag we publish
        const float* bufQ = sEz + (int)((t - 1) & 1u) * (6*NY);
        float*       bufP = sEz + (int)(t & 1u) * (6*NY);

        // ---- gather Ez(t-1) neighbors from smem (overlaps any residual poll latency) ----
        float  ezL = ez.x, ezE = ez.w;
        float4 ezU = ez,   ezD = ez;
        if (act) {
            if (!edgeL)   ezL = bufQ[o - 1];
            if (jq < 99)  ezE = bufQ[o + 4];
            if (upReg)    ezU = *(const float4*)&bufQ[o - NY];
            if (dnReg)    ezD = *(const float4*)&bufQ[o + NY];
        }
        // ---- consume prefetched slots; on stale tag fall back to poll loop ----
        if (spinA) {
            while (a0.x < tf1 || a0.w < tf1 || a1.x < tf1 || a1.w < tf1) {
                a0 = ld_gpu_v4(plA + qo); a1 = ld_gpu_v4(plA + qo + 1);
            }
            ezU = make_float4(a0.y, a0.z, a1.y, a1.z);
        }
        if (spinB) {
            while (b0.x < tf1 || b0.w < tf1 || b1.x < tf1 || b1.w < tf1) {
                b0 = ld_gpu_v4(plB + qo); b1 = ld_gpu_v4(plB + qo + 1);
            }
            ezD = make_float4(b0.y, b0.z, b1.y, b1.z);
        }

        if (act) {
            // ---- halo H recurrences (use Ez(t-1)) ----
            hyU.x = rU * dmp.x * (hyU.x + 0.5f * (ez.x - ezU.x));
            hyU.y = rU * dmp.y * (hyU.y + 0.5f * (ez.y - ezU.y));
            hyU.z = rU * dmp.z * (hyU.z + 0.5f * (ez.z - ezU.z));
            hyU.w = rU * dmp.w * (hyU.w + 0.5f * (ez.w - ezU.w));
            hxW   = rL * dmp.x * (hxW   - 0.5f * (ez.x - ezL));

            // ---- own H ----
            hx.x = dmp.x * (hx.x - 0.5f * (ez.y - ez.x));
            hx.y = dmp.y * (hx.y - 0.5f * (ez.z - ez.y));
            hx.z = dmp.z * (hx.z - 0.5f * (ez.w - ez.z));
            hx.w = dmp.w * (hx.w - 0.5f * (ezE  - ez.w));
            hy.x = dmp.x * (hy.x + 0.5f * (ezD.x - ez.x));
            hy.y = dmp.y * (hy.y + 0.5f * (ezD.y - ez.y));
            hy.z = dmp.z * (hy.z + 0.5f * (ezD.z - ez.z));
            hy.w = dmp.w * (hy.w + 0.5f * (ezD.w - ez.w));

            // ---- E: all registers ----
            float4 hyUe = edgeTop ? hy : hyU;      // i==0: dHy_x = 0
            float  hxWe = edgeL   ? hx.x : hxW;    // j==0: dHx_y = 0
            ez.x = dmp.x * (ez.x + iek.x * ((hy.x - hyUe.x) - (hx.x - hxWe)));
            ez.y = dmp.y * (ez.y + iek.y * ((hy.y - hyUe.y) - (hx.y - hx.x)));
            ez.z = dmp.z * (ez.z + iek.z * ((hy.z - hyUe.z) - (hx.z - hx.y)));
            ez.w = dmp.w * (ez.w + iek.w * ((hy.w - hyUe.w) - (hx.w - hx.z)));

            if (hasSrc) {
                ez.x += Ssin.x;  ez.y += Ssin.y;  ez.z += Ssin.z;  ez.w += Ssin.w;
                float ns, nc;
                ns = Ssin.x * cW + Scos.x * sW; nc = Scos.x * cW - Ssin.x * sW; Ssin.x = ns; Scos.x = nc;
                ns = Ssin.y * cW + Scos.y * sW; nc = Scos.y * cW - Ssin.y * sW; Ssin.y = ns; Scos.y = nc;
                ns = Ssin.z * cW + Scos.z * sW; nc = Scos.z * cW - Ssin.z * sW; Ssin.z = ns; Scos.z = nc;
                ns = Ssin.w * cW + Scos.w * sW; nc = Scos.w * cW - Ssin.w * sW; Ssin.w = ns; Scos.w = nc;
            }

            // ---- publish boundary quads ASAP (protocol covers WAR on parity slots) ----
            if (topT) {
                st_gpu_v4(psT + po,     make_float4(tagf, ez.x, ez.y, tagf));
                st_gpu_v4(psT + po + 1, make_float4(tagf, ez.z, ez.w, tagf));
            }
            if (botT) {
                st_gpu_v4(psB + po,     make_float4(tagf, ez.x, ez.y, tagf));
                st_gpu_v4(psB + po + 1, make_float4(tagf, ez.z, ez.w, tagf));
            }
            *(float4*)&bufP[o] = ez;
        }

        // ---- prefetch next step's halo slots (parity po); latency hidden by the bar ----
        if (spinA) { a0 = ld_gpu_v4(plA + po); a1 = ld_gpu_v4(plA + po + 1); }
        if (spinB) { b0 = ld_gpu_v4(plB + po); b1 = ld_gpu_v4(plB + po + 1); }

        __syncthreads();
    }

    // ---- detector: final Ez at row 370 lives in registers ----
    if (hasDet) {
        const float* ec = &ez.x;
        #pragma unroll
        for (int c = 0; c < 4; ++c) {
            int j = j0 + c;
            int p = (j + 10) / 80 - 1;
            int o2 = (j + 10) - 80 * (p + 1);
            if (p >= 0 && p < 4 && o2 < 20)
                out[batch * 80 + p * 20 + o2] = ec[c];
        }
    }
}

extern "C" void kernel_launch(void* const* d_in, const int* in_sizes, int n_in,
                              void* d_out, int out_size) {
    const float* phases = (const float*)d_in[0];   // (2,4)
    const float* radius = (const float*)d_in[1];   // (8,8)
    float* out = (float*)d_out;                    // (2,4,20)
    setup_kernel<<<(NC + 255) / 256, 256>>>(radius);
    fdtd_kernel<<<NBLK, TPB>>>(phases, out);
}

// round 12
// speedup vs baseline: 4.9743x; 1.0397x over previous
#include <cuda_runtime.h>
#include <math.h>

#define NX 400
#define NY 400
#define NC (NX*NY)
#define STEPS 300
#define NSTRIP 74
#define NBLK (2*NSTRIP)
#define TPB 640
#define SRC_I 30
#define DET_I 370
#define PI_F 3.14159265358979323846f
#define NSLOT 200                  // 2 columns per 16B slot

typedef unsigned long long u64;

// Persistent device state (no allocations allowed)
__device__ float d_ie[NC];                 // COURANT / eps
__device__ float d_damp1[NX];              // 1-D damp profile (x == y)
__device__ float4 d_slT[2*NBLK*NSLOT];     // [parity][blk][slot]: top-row Ez, tag-fused
__device__ float4 d_slB[2*NBLK*NSLOT];     // bottom-row Ez, tag-fused

// GPU-scope relaxed 16B exchange ops (stay in L2)
__device__ __forceinline__ float4 ld_gpu_v4(const float4* p) {
    float4 v;
    asm volatile("ld.relaxed.gpu.global.v4.f32 {%0,%1,%2,%3}, [%4];"
                 : "=f"(v.x), "=f"(v.y), "=f"(v.z), "=f"(v.w) : "l"(p) : "memory");
    return v;
}
__device__ __forceinline__ void st_gpu_v4(float4* p, float4 v) {
    asm volatile("st.relaxed.gpu.global.v4.f32 [%0], {%1,%2,%3,%4};"
                 :: "l"(p), "f"(v.x), "f"(v.y), "f"(v.z), "f"(v.w) : "memory");
}

// ---- packed f32x2 helpers ----
__device__ __forceinline__ u64 pk(float a, float b) {
    u64 r; asm("mov.b64 %0, {%1, %2};" : "=l"(r) : "f"(a), "f"(b)); return r;
}
__device__ __forceinline__ void upk(u64 v, float& a, float& b) {
    asm("mov.b64 {%0, %1}, %2;" : "=f"(a), "=f"(b) : "l"(v));
}
__device__ __forceinline__ u64 f2add(u64 a, u64 b) {
    u64 d; asm("add.rn.f32x2 %0, %1, %2;" : "=l"(d) : "l"(a), "l"(b)); return d;
}
__device__ __forceinline__ u64 f2sub(u64 a, u64 b) {
    u64 d; asm("sub.rn.f32x2 %0, %1, %2;" : "=l"(d) : "l"(a), "l"(b)); return d;
}
__device__ __forceinline__ u64 f2mul(u64 a, u64 b) {
    u64 d; asm("mul.rn.f32x2 %0, %1, %2;" : "=l"(d) : "l"(a), "l"(b)); return d;
}
__device__ __forceinline__ u64 f2fma(u64 a, u64 b, u64 c) {
    u64 d; asm("fma.rn.f32x2 %0, %1, %2, %3;" : "=l"(d) : "l"(a), "l"(b), "l"(c)); return d;
}

// ---------------- setup: eps, damp, zero slot buffers ----------------
__global__ void setup_kernel(const float* __restrict__ radius) {
    int idx = blockIdx.x * blockDim.x + threadIdx.x;
    if (idx < 2*NBLK*NSLOT) {
        d_slT[idx] = make_float4(0.f, 0.f, 0.f, 0.f);   // tag 0 == "step 0 published", Ez=0
        d_slB[idx] = make_float4(0.f, 0.f, 0.f, 0.f);
    }
    if (idx < NX) {
        float v = 1.0f;
        if (idx < 10) {
            float rr = (10 - idx - 0.5f) * 0.1f;
            v = expf(-0.5f * rr * rr * rr);
        } else if (idx >= NX - 10) {
            float rr = (10 - (NX - 1 - idx) - 0.5f) * 0.1f;
            v = expf(-0.5f * rr * rr * rr);
        }
        d_damp1[idx] = v;
    }
    if (idx >= NC) return;
    int i = idx / NY;
    int j = idx - i * NY;
    int p   = (j + 10) / 80 - 1;
    int off = (j + 10) - 80 * (p + 1);
    bool inport = (p >= 0 && p < 4 && off < 20);
    float eps = 1.0f;
    if ((i < SRC_I || i >= DET_I) && inport) eps = 2.8f;
    if (i >= 80 && i < 320 && j >= 80 && j < 320) {
        int X = i - 80, Y = j - 80;
        int a = X / 30, b = Y / 30;
        float r = radius[a * 8 + b];
        if (r < 0.3f) r = 0.0f;
        float dx = (float)(X - (15 + 30 * a));
        float dy = (float)(Y - (15 + 30 * b));
        eps = (dx * dx + dy * dy <= r * r) ? 1.0f : 2.8f;
    }
    d_ie[idx] = 0.5f / eps;
}

// ---------- persistent strip kernel: f32x2-packed quads, register halos, prefetched exchange ----------
__global__ void __launch_bounds__(TPB, 1)
fdtd_kernel(const float* __restrict__ phases, float* __restrict__ out)
{
    __shared__ __align__(16) float sEz[2*6*NY];   // parity double-buffered Ez

    const int bk    = blockIdx.x;
    const int batch = bk / NSTRIP;
    const int s     = bk - batch * NSTRIP;
    const int r0    = (s * NX) / NSTRIP;
    const int r1    = ((s + 1) * NX) / NSTRIP;
    const int h     = r1 - r0;
    const bool hasA = (s > 0);
    const bool hasB = (s < NSTRIP - 1);
    const int tid   = threadIdx.x;
    const int bkA   = hasA ? bk - 1 : bk;
    const int bkB   = hasB ? bk + 1 : bk;

    // warp-priority permutation: boundary rows to highest active warps (hi-wid-first arbiter)
    const int  li   = tid / 100;
    const int  jq   = tid - li * 100;
    const bool act  = (li < h);
    int l;
    if (li == h - 2)      l = 0;       // top row -> 2nd-highest warps
    else if (li == h - 1) l = h - 1;   // bottom row -> highest warps
    else                  l = li + 1;  // interior
    if (!act) l = 0;

    const int  i    = r0 + l;
    const int  j0   = jq * 4;
    const int  o    = l * NY + j0;
    const bool topT = act && (l == 0);
    const bool botT = act && (l == h - 1);
    const bool spinA = topT && hasA;
    const bool spinB = botT && hasB;
    const bool upReg  = act && (l > 0);
    const bool dnReg  = act && (l < h - 1);
    const bool edgeTop = topT && !hasA;
    const bool edgeL   = (jq == 0);

    for (int x = tid; x < 2*6*NY; x += TPB) sEz[x] = 0.f;

    // tag-fused slot pointers (parity offset added per step)
    const float4* plA = d_slB + bkA*NSLOT + 2*jq;   // above's bottom Ez slots
    const float4* plB = d_slT + bkB*NSLOT + 2*jq;   // below's top Ez slots
    float4*       psT = d_slT + bk*NSLOT + 2*jq;    // own top publish
    float4*       psB = d_slB + bk*NSLOT + 2*jq;    // own bottom publish

    // packed state
    u64 ez01 = 0, ez23 = 0, hx01 = 0, hx23 = 0, hy01 = 0, hy23 = 0, hyU01 = 0, hyU23 = 0;
    float hxW = 0.f;
    // packed constants
    u64 c_dmp01 = 0, c_dmp23 = 0, c_iek01 = 0, c_iek23 = 0, c_rU2 = 0;
    const u64 c_half  = pk(0.5f, 0.5f);
    const u64 c_nhalf = pk(-0.5f, -0.5f);
    float rLdmp = 0.f;
    float4 Ssin = {0,0,0,0}, Scos = {0,0,0,0};
    bool hasSrc = false, hasDet = false;

    if (act) {
        float di = d_damp1[i];
        float dmp0 = di * d_damp1[j0],   dmp1 = di * d_damp1[j0+1];
        float dmp2 = di * d_damp1[j0+2], dmp3 = di * d_damp1[j0+3];
        c_dmp01 = pk(dmp0, dmp1); c_dmp23 = pk(dmp2, dmp3);
        float4 iek = *(const float4*)&d_ie[i * NY + j0];
        c_iek01 = pk(iek.x, iek.y); c_iek23 = pk(iek.z, iek.w);
        float rU = (i > 0) ? d_damp1[i - 1] / di : 1.f;
        c_rU2 = pk(rU, rU);
        float rL = (j0 > 0) ? d_damp1[j0 - 1] / d_damp1[j0] : 1.f;
        rLdmp = rL * dmp0;
        if (i == SRC_I || i == DET_I) {
            float* ss = &Ssin.x; float* sc = &Scos.x;
            #pragma unroll
            for (int c = 0; c < 4; ++c) {
                int j = j0 + c;
                int p = (j + 10) / 80 - 1;
                int o2 = (j + 10) - 80 * (p + 1);
                bool inport = (p >= 0 && p < 4 && o2 < 20);
                if (inport && i == SRC_I) {
                    float ps = PI_F * phases[batch * 4 + p];
                    ss[c] = sinf(ps);     // angle at t=1 (tf=0)
                    sc[c] = cosf(ps);
                    hasSrc = true;
                }
                if (inport && i == DET_I) hasDet = true;
            }
        }
    }
    const float W  = (float)(2.0 * 3.14159265358979323846 * (12.5 / 1550.0));
    const float cW = cosf(W), sW = sinf(W);
    __syncthreads();

    // prime the prefetch pipeline: loads for parity 0 (step 1 reads qo=0; init tags==0 are valid)
    float4 a0 = {0,0,0,0}, a1 = {0,0,0,0}, b0 = {0,0,0,0}, b1 = {0,0,0,0};
    if (spinA) { a0 = ld_gpu_v4(plA); a1 = ld_gpu_v4(plA + 1); }
    if (spinB) { b0 = ld_gpu_v4(plB); b1 = ld_gpu_v4(plB + 1); }

    for (unsigned t = 1; t <= STEPS; ++t) {
        const int qo = (int)((t - 1) & 1u) * (NBLK*NSLOT);
        const int po = (int)(t & 1u) * (NBLK*NSLOT);
        const float tf1  = (float)(t - 1);    // tag we need from neighbors
        const float tagf = (float)t;          // tag we publish
        const float* bufQ = sEz + (int)((t - 1) & 1u) * (6*NY);
        float*       bufP = sEz + (int)(t & 1u) * (6*NY);

        // ---- unpack own Ez(t-1); gather neighbors from smem ----
        float e0, e1, e2, e3;
        upk(ez01, e0, e1); upk(ez23, e2, e3);
        float ezL = e0, ezE = e3;
        u64 ezU01 = ez01, ezU23 = ez23, ezD01 = ez01, ezD23 = ez23;
        if (act) {
            if (!edgeL)  ezL = bufQ[o - 1];
            if (jq < 99) ezE = bufQ[o + 4];
            if (upReg) { ulonglong2 u = *(const ulonglong2*)&bufQ[o - NY]; ezU01 = u.x; ezU23 = u.y; }
            if (dnReg) { ulonglong2 u = *(const ulonglong2*)&bufQ[o + NY]; ezD01 = u.x; ezD23 = u.y; }
        }
        // ---- consume prefetched slots; on stale tag fall back to poll loop ----
        if (spinA) {
            while (a0.x < tf1 || a0.w < tf1 || a1.x < tf1 || a1.w < tf1) {
                a0 = ld_gpu_v4(plA + qo); a1 = ld_gpu_v4(plA + qo + 1);
            }
            ezU01 = pk(a0.y, a0.z); ezU23 = pk(a1.y, a1.z);
        }
        if (spinB) {
            while (b0.x < tf1 || b0.w < tf1 || b1.x < tf1 || b1.w < tf1) {
                b0 = ld_gpu_v4(plB + qo); b1 = ld_gpu_v4(plB + qo + 1);
            }
            ezD01 = pk(b0.y, b0.z); ezD23 = pk(b1.y, b1.z);
        }

        if (act) {
            const u64 ezR01 = pk(e1, e2);
            const u64 ezR23 = pk(e3, ezE);

            // ---- H phase (identical rounding to scalar version) ----
            // hx = dmp * (hx - 0.5*(ezR - ez))
            hx01 = f2mul(c_dmp01, f2fma(c_nhalf, f2sub(ezR01, ez01), hx01));
            hx23 = f2mul(c_dmp23, f2fma(c_nhalf, f2sub(ezR23, ez23), hx23));
            // hy = dmp * (hy + 0.5*(ezD - ez))
            hy01 = f2mul(c_dmp01, f2fma(c_half, f2sub(ezD01, ez01), hy01));
            hy23 = f2mul(c_dmp23, f2fma(c_half, f2sub(ezD23, ez23), hy23));
            // hyU = rU * dmp * (hyU + 0.5*(ez - ezU))
            hyU01 = f2mul(c_rU2, f2mul(c_dmp01, f2fma(c_half, f2sub(ez01, ezU01), hyU01)));
            hyU23 = f2mul(c_rU2, f2mul(c_dmp23, f2fma(c_half, f2sub(ez23, ezU23), hyU23)));
            // hxW = rL*dmp0 * (hxW - 0.5*(e0 - ezL))
            hxW = rLdmp * __fmaf_rn(-0.5f, e0 - ezL, hxW);

            // ---- E phase: all registers ----
            float h0, h1, h2, h3;
            upk(hx01, h0, h1); upk(hx23, h2, h3);
            const u64 hxL01 = pk(edgeL ? h0 : hxW, h0);
            const u64 hxL23 = pk(h1, h2);
            const u64 hyUe01 = edgeTop ? hy01 : hyU01;
            const u64 hyUe23 = edgeTop ? hy23 : hyU23;
            // ez = dmp * (ez + iek*((hy - hyUe) - (hx - hxL)))
            u64 d01 = f2sub(f2sub(hy01, hyUe01), f2sub(hx01, hxL01));
            u64 d23 = f2sub(f2sub(hy23, hyUe23), f2sub(hx23, hxL23));
            ez01 = f2mul(c_dmp01, f2fma(c_iek01, d01, ez01));
            ez23 = f2mul(c_dmp23, f2fma(c_iek23, d23, ez23));

            if (hasSrc) {
                float g0, g1, g2, g3;
                upk(ez01, g0, g1); upk(ez23, g2, g3);
                g0 += Ssin.x; g1 += Ssin.y; g2 += Ssin.z; g3 += Ssin.w;
                ez01 = pk(g0, g1); ez23 = pk(g2, g3);
                float ns, nc;
                ns = Ssin.x * cW + Scos.x * sW; nc = Scos.x * cW - Ssin.x * sW; Ssin.x = ns; Scos.x = nc;
                ns = Ssin.y * cW + Scos.y * sW; nc = Scos.y * cW - Ssin.y * sW; Ssin.y = ns; Scos.y = nc;
                ns = Ssin.z * cW + Scos.z * sW; nc = Scos.z * cW - Ssin.z * sW; Ssin.z = ns; Scos.z = nc;
                ns = Ssin.w * cW + Scos.w * sW; nc = Scos.w * cW - Ssin.w * sW; Ssin.w = ns; Scos.w = nc;
            }

            // ---- publish boundary quads ASAP (protocol covers WAR on parity slots) ----
            if (topT | botT) {
                float p0, p1, p2, p3;
                upk(ez01, p0, p1); upk(ez23, p2, p3);
                if (topT) {
                    st_gpu_v4(psT + po,     make_float4(tagf, p0, p1, tagf));
                    st_gpu_v4(psT + po + 1, make_float4(tagf, p2, p3, tagf));
                }
                if (botT) {
                    st_gpu_v4(psB + po,     make_float4(tagf, p0, p1, tagf));
                    st_gpu_v4(psB + po + 1, make_float4(tagf, p2, p3, tagf));
                }
            }
            ulonglong2 st2; st2.x = ez01; st2.y = ez23;
            *(ulonglong2*)&bufP[o] = st2;
        }

        // ---- prefetch next step's halo slots (parity po); latency hidden by the bar ----
        if (spinA) { a0 = ld_gpu_v4(plA + po); a1 = ld_gpu_v4(plA + po + 1); }
        if (spinB) { b0 = ld_gpu_v4(plB + po); b1 = ld_gpu_v4(plB + po + 1); }

        __syncthreads();
    }

    // ---- detector: final Ez at row 370 lives in registers ----
    if (hasDet) {
        float e0, e1, e2, e3;
        upk(ez01, e0, e1); upk(ez23, e2, e3);
        float ec[4] = {e0, e1, e2, e3};
        #pragma unroll
        for (int c = 0; c < 4; ++c) {
            int j = j0 + c;
            int p = (j + 10) / 80 - 1;
            int o2 = (j + 10) - 80 * (p + 1);
            if (p >= 0 && p < 4 && o2 < 20)
                out[batch * 80 + p * 20 + o2] = ec[c];
        }
    }
}

extern "C" void kernel_launch(void* const* d_in, const int* in_sizes, int n_in,
                              void* d_out, int out_size) {
    const float* phases = (const float*)d_in[0];   // (2,4)
    const float* radius = (const float*)d_in[1];   // (8,8)
    float* out = (float*)d_out;                    // (2,4,20)
    setup_kernel<<<(NC + 255) / 256, 256>>>(radius);
    fdtd_kernel<<<NBLK, TPB>>>(phases, out);
}